// round 2
// baseline (speedup 1.0000x reference)
#include <cuda_runtime.h>
#include <math.h>

#define BATCH 2
#define SEQ   2048
#define CDIM  2048
#define NHEAD 16
#define NKV   4
#define HD    128
#define NREP  4              // NHEAD / NKV
#define WIN   512
#define FDIM  3072           // (NHEAD + 2*NKV) * HD
#define ATT_SCALE 0.08838834764831845f  // 1/sqrt(128)

// Scratch (allocation-free rule: __device__ globals)
__device__ float g_qkv[(size_t)BATCH * SEQ * FDIM]; // 50.3 MB
__device__ float g_y  [(size_t)BATCH * SEQ * CDIM]; // 33.6 MB

// ---------------------------------------------------------------------------
// Generic NT SGEMM: C[M,N] = A[M,K] * B[N,K]^T   (both operands K-major)
// 128x128 block tile, BK=16, 256 threads, 8x8 micro-tile per thread.
// M % 128 == 0, N % 128 == 0, K % 16 == 0 guaranteed by problem sizes.
// ---------------------------------------------------------------------------
__global__ void __launch_bounds__(256) sgemm_nt_kernel(
    const float* __restrict__ A, const float* __restrict__ B,
    float* __restrict__ C, int M, int N, int K)
{
    constexpr int BM = 128, BN = 128, BK = 16;
    __shared__ float As[BK][BM];   // transposed: As[k][m]
    __shared__ float Bs[BK][BN];   // transposed: Bs[k][n]

    const int tid = threadIdx.x;
    const int tx = tid & 15;       // 0..15
    const int ty = tid >> 4;       // 0..15
    const int m0 = blockIdx.y * BM;
    const int n0 = blockIdx.x * BN;

    float acc[8][8] = {};

    for (int k0 = 0; k0 < K; k0 += BK) {
        // Load A tile (BM x BK) -> As[k][m], vectorized along k
        #pragma unroll
        for (int v = tid; v < BM * BK / 4; v += 256) {
            int m  = v >> 2;            // v / (BK/4)
            int kq = (v & 3) * 4;
            float4 a = *(const float4*)&A[(size_t)(m0 + m) * K + k0 + kq];
            As[kq + 0][m] = a.x; As[kq + 1][m] = a.y;
            As[kq + 2][m] = a.z; As[kq + 3][m] = a.w;
        }
        // Load B tile (BN x BK) -> Bs[k][n]
        #pragma unroll
        for (int v = tid; v < BN * BK / 4; v += 256) {
            int n  = v >> 2;
            int kq = (v & 3) * 4;
            float4 b = *(const float4*)&B[(size_t)(n0 + n) * K + k0 + kq];
            Bs[kq + 0][n] = b.x; Bs[kq + 1][n] = b.y;
            Bs[kq + 2][n] = b.z; Bs[kq + 3][n] = b.w;
        }
        __syncthreads();

        #pragma unroll
        for (int k = 0; k < BK; ++k) {
            float4 a0 = *(const float4*)&As[k][ty * 8];
            float4 a1 = *(const float4*)&As[k][ty * 8 + 4];
            float4 b0 = *(const float4*)&Bs[k][tx * 8];
            float4 b1 = *(const float4*)&Bs[k][tx * 8 + 4];
            float a[8] = {a0.x, a0.y, a0.z, a0.w, a1.x, a1.y, a1.z, a1.w};
            float b[8] = {b0.x, b0.y, b0.z, b0.w, b1.x, b1.y, b1.z, b1.w};
            #pragma unroll
            for (int i = 0; i < 8; ++i)
                #pragma unroll
                for (int j = 0; j < 8; ++j)
                    acc[i][j] += a[i] * b[j];
        }
        __syncthreads();
    }

    #pragma unroll
    for (int i = 0; i < 8; ++i) {
        int m = m0 + ty * 8 + i;
        float4* crow = (float4*)&C[(size_t)m * N + n0 + tx * 8];
        crow[0] = make_float4(acc[i][0], acc[i][1], acc[i][2], acc[i][3]);
        crow[1] = make_float4(acc[i][4], acc[i][5], acc[i][6], acc[i][7]);
    }
}

// ---------------------------------------------------------------------------
// RoPE in-place over Q (heads 0..15) and K (heads 16..19) portions of g_qkv.
// One thread per (token, head, pair).
// ---------------------------------------------------------------------------
__global__ void rope_kernel(const float* __restrict__ fcos,
                            const float* __restrict__ fsin)
{
    const int PAIRS_PER_TOK = (NHEAD + NKV) * (HD / 2);  // 1280
    int idx = blockIdx.x * blockDim.x + threadIdx.x;
    if (idx >= BATCH * SEQ * PAIRS_PER_TOK) return;

    int tok = idx / PAIRS_PER_TOK;
    int r   = idx % PAIRS_PER_TOK;
    int t   = tok % SEQ;
    int h   = r / (HD / 2);   // 0..19 (q heads 0..15, k heads 16..19)
    int p   = r % (HD / 2);

    float c = __ldg(&fcos[t * (HD / 2) + p]);
    float s = __ldg(&fsin[t * (HD / 2) + p]);

    float* base = &g_qkv[(size_t)tok * FDIM + h * HD + 2 * p];
    float xr = base[0], xi = base[1];
    base[0] = xr * c - xi * s;
    base[1] = xr * s + xi * c;
}

// ---------------------------------------------------------------------------
// Windowed-causal flash attention, fp32.
// Block = (64 queries) x (one b,h). 256 threads (16x16), S micro 4x4, O 4x8.
// Key tiles of 64; window of 512 => at most 9 key tiles per query tile.
// ---------------------------------------------------------------------------
#define ATT_SMEM_FLOATS (128*64 /*Qs*/ + 128*64 /*KVs*/ + 64*65 /*Ps*/)

__global__ void __launch_bounds__(256) attn_kernel()
{
    extern __shared__ float smem[];
    float* Qs  = smem;                 // [k(128)][m(64)]  Q transposed
    float* KVs = smem + 128 * 64;      // K phase: [k(128)][c(64)]; V phase: [j(64)][d(128)]
    float* Ps  = smem + 2 * 128 * 64;  // [64][65]

    const int tid = threadIdx.x;
    const int tx = tid & 15, ty = tid >> 4;
    const int bh  = blockIdx.y;
    const int b   = bh / NHEAD;
    const int h   = bh % NHEAD;
    const int kvh = h / NREP;
    const int q0  = blockIdx.x * 64;

    // Load Q tile transposed: Qs[d][m]
    #pragma unroll
    for (int v = tid; v < 64 * 32; v += 256) {
        int m  = v >> 5;
        int dq = (v & 31) * 4;
        float4 q = *(const float4*)&g_qkv[(size_t)(b * SEQ + q0 + m) * FDIM + h * HD + dq];
        Qs[(dq + 0) * 64 + m] = q.x; Qs[(dq + 1) * 64 + m] = q.y;
        Qs[(dq + 2) * 64 + m] = q.z; Qs[(dq + 3) * 64 + m] = q.w;
    }

    float m_i[4], l_i[4], O[4][8];
    #pragma unroll
    for (int i = 0; i < 4; ++i) {
        m_i[i] = -1e30f; l_i[i] = 0.f;
        #pragma unroll
        for (int j = 0; j < 8; ++j) O[i][j] = 0.f;
    }

    const int kt_lo = (q0 >= WIN) ? (q0 - WIN) : 0;

    for (int kt = kt_lo; kt <= q0; kt += 64) {
        // ---- load K tile transposed: KVs[d][c] ----
        #pragma unroll
        for (int v = tid; v < 64 * 32; v += 256) {
            int c  = v >> 5;
            int dq = (v & 31) * 4;
            float4 k = *(const float4*)&g_qkv[(size_t)(b * SEQ + kt + c) * FDIM
                                              + NHEAD * HD + kvh * HD + dq];
            KVs[(dq + 0) * 64 + c] = k.x; KVs[(dq + 1) * 64 + c] = k.y;
            KVs[(dq + 2) * 64 + c] = k.z; KVs[(dq + 3) * 64 + c] = k.w;
        }
        __syncthreads();

        // ---- S = Q K^T (4x4 per thread) ----
        float s[4][4] = {};
        #pragma unroll 4
        for (int k = 0; k < HD; ++k) {
            float4 a = *(const float4*)&Qs[k * 64 + ty * 4];
            float4 bb = *(const float4*)&KVs[k * 64 + tx * 4];
            float av[4] = {a.x, a.y, a.z, a.w};
            float bv[4] = {bb.x, bb.y, bb.z, bb.w};
            #pragma unroll
            for (int i = 0; i < 4; ++i)
                #pragma unroll
                for (int j = 0; j < 4; ++j)
                    s[i][j] += av[i] * bv[j];
        }

        // ---- mask + scale ----
        #pragma unroll
        for (int i = 0; i < 4; ++i) {
            int qi = q0 + ty * 4 + i;
            #pragma unroll
            for (int j = 0; j < 4; ++j) {
                int kj = kt + tx * 4 + j;
                bool keep = (kj <= qi) && (kj >= qi - (WIN - 1));
                s[i][j] = keep ? s[i][j] * ATT_SCALE : -1e30f;
            }
        }

        // ---- online softmax ----
        float p[4][4];
        #pragma unroll
        for (int i = 0; i < 4; ++i) {
            float rm = fmaxf(fmaxf(s[i][0], s[i][1]), fmaxf(s[i][2], s[i][3]));
            #pragma unroll
            for (int o = 1; o < 16; o <<= 1)
                rm = fmaxf(rm, __shfl_xor_sync(0xffffffffu, rm, o));
            float m_new = fmaxf(m_i[i], rm);
            float alpha = __expf(m_i[i] - m_new);
            float rs = 0.f;
            #pragma unroll
            for (int j = 0; j < 4; ++j) {
                p[i][j] = __expf(s[i][j] - m_new);
                rs += p[i][j];
            }
            #pragma unroll
            for (int o = 1; o < 16; o <<= 1)
                rs += __shfl_xor_sync(0xffffffffu, rs, o);
            l_i[i] = l_i[i] * alpha + rs;
            m_i[i] = m_new;
            #pragma unroll
            for (int j = 0; j < 8; ++j) O[i][j] *= alpha;
        }

        // ---- P to smem ----
        #pragma unroll
        for (int i = 0; i < 4; ++i)
            #pragma unroll
            for (int j = 0; j < 4; ++j)
                Ps[(ty * 4 + i) * 65 + tx * 4 + j] = p[i][j];
        __syncthreads();   // P visible; K reads done

        // ---- load V tile: KVs[j][d] ----
        #pragma unroll
        for (int v = tid; v < 64 * 32; v += 256) {
            int j  = v >> 5;
            int dq = (v & 31) * 4;
            *(float4*)&KVs[j * 128 + dq] =
                *(const float4*)&g_qkv[(size_t)(b * SEQ + kt + j) * FDIM
                                       + (NHEAD + NKV) * HD + kvh * HD + dq];
        }
        __syncthreads();

        // ---- O += P V ----
        #pragma unroll 4
        for (int jj = 0; jj < 64; ++jj) {
            float4 v0 = *(const float4*)&KVs[jj * 128 + tx * 8];
            float4 v1 = *(const float4*)&KVs[jj * 128 + tx * 8 + 4];
            #pragma unroll
            for (int i = 0; i < 4; ++i) {
                float pv = Ps[(ty * 4 + i) * 65 + jj];
                O[i][0] += pv * v0.x; O[i][1] += pv * v0.y;
                O[i][2] += pv * v0.z; O[i][3] += pv * v0.w;
                O[i][4] += pv * v1.x; O[i][5] += pv * v1.y;
                O[i][6] += pv * v1.z; O[i][7] += pv * v1.w;
            }
        }
        __syncthreads();   // before next K load overwrites KVs
    }

    // ---- normalize and write y ----
    #pragma unroll
    for (int i = 0; i < 4; ++i) {
        float inv_l = 1.f / l_i[i];
        int q = q0 + ty * 4 + i;
        float* yrow = &g_y[(size_t)(b * SEQ + q) * CDIM + h * HD + tx * 8];
        *(float4*)&yrow[0] = make_float4(O[i][0] * inv_l, O[i][1] * inv_l,
                                         O[i][2] * inv_l, O[i][3] * inv_l);
        *(float4*)&yrow[4] = make_float4(O[i][4] * inv_l, O[i][5] * inv_l,
                                         O[i][6] * inv_l, O[i][7] * inv_l);
    }
}

// ---------------------------------------------------------------------------
extern "C" void kernel_launch(void* const* d_in, const int* in_sizes, int n_in,
                              void* d_out, int out_size)
{
    (void)in_sizes; (void)n_in; (void)out_size;
    const float* x      = (const float*)d_in[0];
    const float* w_qkv  = (const float*)d_in[1];
    const float* w_proj = (const float*)d_in[2];
    const float* fcos   = (const float*)d_in[3];
    const float* fsin   = (const float*)d_in[4];
    // d_in[5] (mask) unused: keep == causal AND window, computed analytically.
    float* out = (float*)d_out;

    void *p_qkv = nullptr, *p_y = nullptr;
    cudaGetSymbolAddress(&p_qkv, g_qkv);
    cudaGetSymbolAddress(&p_y, g_y);
    float* qkv = (float*)p_qkv;
    float* y   = (float*)p_y;

    const int M = BATCH * SEQ;  // 4096

    // 1) QKV projection
    {
        dim3 grid(FDIM / 128, M / 128);
        sgemm_nt_kernel<<<grid, 256>>>(x, w_qkv, qkv, M, FDIM, CDIM);
    }
    // 2) RoPE (in place on q,k portions)
    {
        const int total = BATCH * SEQ * (NHEAD + NKV) * (HD / 2);
        rope_kernel<<<(total + 255) / 256, 256>>>(fcos, fsin);
    }
    // 3) Windowed flash attention
    {
        static_assert(ATT_SMEM_FLOATS * 4 < 228 * 1024, "smem");
        cudaFuncSetAttribute(attn_kernel,
                             cudaFuncAttributeMaxDynamicSharedMemorySize,
                             ATT_SMEM_FLOATS * 4);
        dim3 grid(SEQ / 64, BATCH * NHEAD);
        attn_kernel<<<grid, 256, ATT_SMEM_FLOATS * 4>>>();
    }
    // 4) Output projection
    {
        dim3 grid(CDIM / 128, M / 128);
        sgemm_nt_kernel<<<grid, 256>>>(y, w_proj, out, M, CDIM, CDIM);
    }
}

// round 6
// speedup vs baseline: 1.9356x; 1.9356x over previous
#include <cuda_runtime.h>
#include <cuda_bf16.h>
#include <cstdint>
#include <math.h>

#define BATCH 2
#define SEQ   2048
#define CDIM  2048
#define NHEAD 16
#define NKV   4
#define HD    128
#define NREP  4
#define WIN   512
#define FDIM  3072
#define MTOT  (BATCH*SEQ)   // 4096
#define ATT_SCALE 0.08838834764831845f

// ---------------- scratch (__device__ globals; no allocations) -------------
__device__ float g_qkv[(size_t)MTOT * FDIM];           // 50.3 MB
__device__ float g_y  [(size_t)MTOT * CDIM];           // 33.6 MB
__device__ __nv_bfloat16 g_xh[(size_t)MTOT * CDIM];
__device__ __nv_bfloat16 g_xl[(size_t)MTOT * CDIM];
__device__ __nv_bfloat16 g_wqh[(size_t)FDIM * CDIM];
__device__ __nv_bfloat16 g_wql[(size_t)FDIM * CDIM];
__device__ __nv_bfloat16 g_wph[(size_t)CDIM * CDIM];
__device__ __nv_bfloat16 g_wpl[(size_t)CDIM * CDIM];
__device__ __nv_bfloat16 g_yh[(size_t)MTOT * CDIM];
__device__ __nv_bfloat16 g_yl[(size_t)MTOT * CDIM];

// ---------------- helpers --------------------------------------------------
__device__ __forceinline__ uint32_t smem_to_u32(const void* p) {
    uint32_t a;
    asm("{ .reg .u64 t; cvta.to.shared.u64 t, %1; cvt.u32.u64 %0, t; }" : "=r"(a) : "l"(p));
    return a;
}
__device__ __forceinline__ void cp_async16(uint32_t dst, const void* src) {
    asm volatile("cp.async.cg.shared.global [%0], [%1], 16;" :: "r"(dst), "l"(src));
}
__device__ __forceinline__ void cp_commit() {
    asm volatile("cp.async.commit_group;");
}
template <int N>
__device__ __forceinline__ void cp_wait() {
    asm volatile("cp.async.wait_group %0;" :: "n"(N));
}
__device__ __forceinline__ void ldmatrix_x4(uint32_t* r, uint32_t addr) {
    asm volatile("ldmatrix.sync.aligned.m8n8.x4.shared.b16 {%0,%1,%2,%3}, [%4];"
        : "=r"(r[0]), "=r"(r[1]), "=r"(r[2]), "=r"(r[3]) : "r"(addr));
}
__device__ __forceinline__ void mma_bf16(float* c, const uint32_t* a, const uint32_t* b) {
    asm volatile(
        "mma.sync.aligned.m16n8k16.row.col.f32.bf16.bf16.f32 "
        "{%0,%1,%2,%3}, {%4,%5,%6,%7}, {%8,%9}, {%0,%1,%2,%3};"
        : "+f"(c[0]), "+f"(c[1]), "+f"(c[2]), "+f"(c[3])
        : "r"(a[0]), "r"(a[1]), "r"(a[2]), "r"(a[3]), "r"(b[0]), "r"(b[1]));
}

// ---------------- split fp32 -> bf16 hi + bf16 lo --------------------------
__global__ void split_kernel(const float* __restrict__ src,
                             __nv_bfloat16* __restrict__ hi,
                             __nv_bfloat16* __restrict__ lo, int n)
{
    int i = blockIdx.x * blockDim.x + threadIdx.x;
    if (i >= n) return;
    float v = src[i];
    __nv_bfloat16 h = __float2bfloat16(v);
    hi[i] = h;
    lo[i] = __float2bfloat16(v - __bfloat162float(h));
}

// ---------------- bf16x3 NT GEMM via mma.sync ------------------------------
// C[M,N] = A[M,K]*B[N,K]^T ~ AhBh + AhBl + AlBh (fp32 accum)
// CTA 128x128, BK=32, 8 warps (2 m x 4 n), warp tile 64x32.
// smem per matrix tile: 128 rows x 40 bf16 (32 data + 8 pad) = 10240 B
#define GPAD     40
#define GROW_B   (GPAD * 2)            // 80 bytes per smem row
#define GMAT_B   (128 * GROW_B)        // 10240
#define GSTG_B   (4 * GMAT_B)          // Ah, Al, Bh, Bl = 40960
#define GEMM_SMEM (2 * GSTG_B)         // 81920

__global__ void __launch_bounds__(256)
gemm_bf16x3_kernel(const __nv_bfloat16* __restrict__ Ah, const __nv_bfloat16* __restrict__ Al,
                   const __nv_bfloat16* __restrict__ Bh, const __nv_bfloat16* __restrict__ Bl,
                   float* __restrict__ C, int M, int N, int K)
{
    extern __shared__ __align__(128) char smem[];
    const uint32_t sbase = smem_to_u32(smem);

    const int tid  = threadIdx.x;
    const int wid  = tid >> 5;
    const int lane = tid & 31;
    const int warp_m = wid & 1;        // 0..1
    const int warp_n = wid >> 1;       // 0..3
    const int m0 = blockIdx.y * 128;
    const int n0 = blockIdx.x * 128;

    float acc[4][4][4];                // [mt][nt][reg]
    #pragma unroll
    for (int i = 0; i < 4; ++i)
        #pragma unroll
        for (int j = 0; j < 4; ++j)
            #pragma unroll
            for (int r = 0; r < 4; ++r) acc[i][j][r] = 0.f;

    const int NIT = K >> 5;            // K/32

    // per-thread load coords: 2 chunks of 16B per matrix per stage
    // chunk = tid + i*256 (0..511); row = chunk/4; col16 = chunk%4
    auto issue_stage = [&](int it) {
        const int s = it & 1;
        const int k0 = it * 32;
        const char* gA[4] = {
            (const char*)(Ah + (size_t)m0 * K + k0), (const char*)(Al + (size_t)m0 * K + k0),
            (const char*)(Bh + (size_t)n0 * K + k0), (const char*)(Bl + (size_t)n0 * K + k0)};
        const size_t grs = (size_t)K * 2;     // gmem row stride bytes
        #pragma unroll
        for (int t = 0; t < 4; ++t) {
            #pragma unroll
            for (int i = 0; i < 2; ++i) {
                int chunk = tid + i * 256;
                int r = chunk >> 2, c = (chunk & 3) * 16;
                uint32_t dst = sbase + s * GSTG_B + t * GMAT_B + r * GROW_B + c;
                cp_async16(dst, gA[t] + (size_t)r * grs + c);
            }
        }
        cp_commit();
    };

    issue_stage(0);

    for (int it = 0; it < NIT; ++it) {
        if (it + 1 < NIT) issue_stage(it + 1);
        if (it + 1 < NIT) cp_wait<1>(); else cp_wait<0>();
        __syncthreads();

        const int s = it & 1;
        const uint32_t sA_h = sbase + s * GSTG_B + 0 * GMAT_B;
        const uint32_t sA_l = sbase + s * GSTG_B + 1 * GMAT_B;
        const uint32_t sB_h = sbase + s * GSTG_B + 2 * GMAT_B;
        const uint32_t sB_l = sbase + s * GSTG_B + 3 * GMAT_B;

        const int lg = lane >> 3;          // 0..3
        #pragma unroll
        for (int ks = 0; ks < 2; ++ks) {
            const int kc = ks * 16;
            // A fragments: rows warp_m*64 + mt*16 + (lane&7) + (lg&1)*8, col kc + (lg>>1)*8
            uint32_t ah[4][4], al[4][4];
            #pragma unroll
            for (int mt = 0; mt < 4; ++mt) {
                uint32_t off = (uint32_t)((warp_m * 64 + mt * 16 + (lane & 7) + (lg & 1) * 8) * GROW_B
                                          + (kc + (lg >> 1) * 8) * 2);
                ldmatrix_x4(ah[mt], sA_h + off);
                ldmatrix_x4(al[mt], sA_l + off);
            }
            // B fragments: two x4 loads cover 4 ntiles
            // lanes 0-7: rows p*16+0..7 @kc ; 8-15: same rows @kc+8 ; 16-23: rows+8 @kc ; 24-31: rows+8 @kc+8
            uint32_t bh[2][4], bl[2][4];
            #pragma unroll
            for (int p = 0; p < 2; ++p) {
                uint32_t off = (uint32_t)((warp_n * 32 + p * 16 + (lane & 7) + (lg >> 1) * 8) * GROW_B
                                          + (kc + (lg & 1) * 8) * 2);
                ldmatrix_x4(bh[p], sB_h + off);
                ldmatrix_x4(bl[p], sB_l + off);
            }
            #pragma unroll
            for (int mt = 0; mt < 4; ++mt)
                #pragma unroll
                for (int nt = 0; nt < 4; ++nt) {
                    const uint32_t* bhp = &bh[nt >> 1][(nt & 1) * 2];
                    const uint32_t* blp = &bl[nt >> 1][(nt & 1) * 2];
                    mma_bf16(acc[mt][nt], ah[mt], bhp);
                    mma_bf16(acc[mt][nt], ah[mt], blp);
                    mma_bf16(acc[mt][nt], al[mt], bhp);
                }
        }
        __syncthreads();
    }

    // epilogue: direct fp32 stores
    #pragma unroll
    for (int mt = 0; mt < 4; ++mt) {
        #pragma unroll
        for (int nt = 0; nt < 4; ++nt) {
            int m = m0 + warp_m * 64 + mt * 16 + (lane >> 2);
            int n = n0 + warp_n * 32 + nt * 8 + (lane & 3) * 2;
            *(float2*)&C[(size_t)m * N + n]       = make_float2(acc[mt][nt][0], acc[mt][nt][1]);
            *(float2*)&C[(size_t)(m + 8) * N + n] = make_float2(acc[mt][nt][2], acc[mt][nt][3]);
        }
    }
}

// ---------------- RoPE -----------------------------------------------------
__global__ void rope_kernel(const float* __restrict__ fcos,
                            const float* __restrict__ fsin)
{
    const int PAIRS_PER_TOK = (NHEAD + NKV) * (HD / 2);  // 1280
    int idx = blockIdx.x * blockDim.x + threadIdx.x;
    if (idx >= MTOT * PAIRS_PER_TOK) return;
    int tok = idx / PAIRS_PER_TOK;
    int r = idx % PAIRS_PER_TOK;
    int t = tok % SEQ;
    int h = r / (HD / 2);
    int p = r % (HD / 2);
    float c = __ldg(&fcos[t * (HD / 2) + p]);
    float s = __ldg(&fsin[t * (HD / 2) + p]);
    float* base = &g_qkv[(size_t)tok * FDIM + h * HD + 2 * p];
    float xr = base[0], xi = base[1];
    base[0] = xr * c - xi * s;
    base[1] = xr * s + xi * c;
}

// ---------------- windowed flash attention, fp32, 128x128 tiles ------------
#define ATT_PS 132
#define ATT_SMEM_FLOATS (128*128 /*Qs*/ + 128*128 /*KVs*/ + 128*ATT_PS /*Ps*/)

__global__ void __launch_bounds__(256) attn_kernel()
{
    extern __shared__ float smem_f[];
    float* Qs  = smem_f;                   // [d(128)][m(128)]
    float* KVs = smem_f + 128 * 128;       // K: [d][c]; V: [c][d]
    float* Ps  = smem_f + 2 * 128 * 128;   // [128][ATT_PS]

    const int tid = threadIdx.x;
    const int tx = tid & 15, ty = tid >> 4;
    const int bh = blockIdx.y;
    const int b = bh / NHEAD;
    const int h = bh % NHEAD;
    const int kvh = h / NREP;
    const int q0 = blockIdx.x * 128;

    // Q tile transposed
    #pragma unroll
    for (int i = 0; i < 16; ++i) {
        int v = tid + i * 256;              // 0..4095
        int m = v >> 5, dq = (v & 31) * 4;
        float4 q = *(const float4*)&g_qkv[(size_t)(b * SEQ + q0 + m) * FDIM + h * HD + dq];
        Qs[(dq + 0) * 128 + m] = q.x; Qs[(dq + 1) * 128 + m] = q.y;
        Qs[(dq + 2) * 128 + m] = q.z; Qs[(dq + 3) * 128 + m] = q.w;
    }

    float m_i[8], l_i[8], O[8][8];
    #pragma unroll
    for (int i = 0; i < 8; ++i) {
        m_i[i] = -1e30f; l_i[i] = 0.f;
        #pragma unroll
        for (int j = 0; j < 8; ++j) O[i][j] = 0.f;
    }

    const int kt_lo = (q0 >= WIN) ? (q0 - WIN) : 0;

    for (int kt = kt_lo; kt <= q0; kt += 128) {
        // K tile transposed: KVs[d][c]
        #pragma unroll
        for (int i = 0; i < 16; ++i) {
            int v = tid + i * 256;
            int c = v >> 5, dq = (v & 31) * 4;
            float4 k = *(const float4*)&g_qkv[(size_t)(b * SEQ + kt + c) * FDIM
                                              + NHEAD * HD + kvh * HD + dq];
            KVs[(dq + 0) * 128 + c] = k.x; KVs[(dq + 1) * 128 + c] = k.y;
            KVs[(dq + 2) * 128 + c] = k.z; KVs[(dq + 3) * 128 + c] = k.w;
        }
        __syncthreads();

        // S = Q K^T : 8x8 per thread
        float s[8][8] = {};
        #pragma unroll 4
        for (int k = 0; k < HD; ++k) {
            float4 a0 = *(const float4*)&Qs[k * 128 + ty * 8];
            float4 a1 = *(const float4*)&Qs[k * 128 + ty * 8 + 4];
            float4 b0 = *(const float4*)&KVs[k * 128 + tx * 8];
            float4 b1 = *(const float4*)&KVs[k * 128 + tx * 8 + 4];
            float av[8] = {a0.x, a0.y, a0.z, a0.w, a1.x, a1.y, a1.z, a1.w};
            float bv[8] = {b0.x, b0.y, b0.z, b0.w, b1.x, b1.y, b1.z, b1.w};
            #pragma unroll
            for (int i = 0; i < 8; ++i)
                #pragma unroll
                for (int j = 0; j < 8; ++j)
                    s[i][j] += av[i] * bv[j];
        }

        // mask + scale + online softmax
        #pragma unroll
        for (int i = 0; i < 8; ++i) {
            int qi = q0 + ty * 8 + i;
            #pragma unroll
            for (int j = 0; j < 8; ++j) {
                int kj = kt + tx * 8 + j;
                bool keep = (kj <= qi) && (kj >= qi - (WIN - 1));
                s[i][j] = keep ? s[i][j] * ATT_SCALE : -1e30f;
            }
            float rm = s[i][0];
            #pragma unroll
            for (int j = 1; j < 8; ++j) rm = fmaxf(rm, s[i][j]);
            #pragma unroll
            for (int o = 1; o < 16; o <<= 1)
                rm = fmaxf(rm, __shfl_xor_sync(0xffffffffu, rm, o));
            float m_new = fmaxf(m_i[i], rm);
            float alpha = __expf(m_i[i] - m_new);
            float rs = 0.f;
            #pragma unroll
            for (int j = 0; j < 8; ++j) {
                s[i][j] = __expf(s[i][j] - m_new);
                rs += s[i][j];
            }
            #pragma unroll
            for (int o = 1; o < 16; o <<= 1)
                rs += __shfl_xor_sync(0xffffffffu, rs, o);
            l_i[i] = l_i[i] * alpha + rs;
            m_i[i] = m_new;
            #pragma unroll
            for (int j = 0; j < 8; ++j) O[i][j] *= alpha;
            // write P row
            *(float4*)&Ps[(ty * 8 + i) * ATT_PS + tx * 8] =
                make_float4(s[i][0], s[i][1], s[i][2], s[i][3]);
            *(float4*)&Ps[(ty * 8 + i) * ATT_PS + tx * 8 + 4] =
                make_float4(s[i][4], s[i][5], s[i][6], s[i][7]);
        }
        __syncthreads();   // S-phase reads of KVs done; P visible

        // V tile: KVs[c][d]
        #pragma unroll
        for (int i = 0; i < 16; ++i) {
            int v = tid + i * 256;
            int c = v >> 5, dq = (v & 31) * 4;
            *(float4*)&KVs[c * 128 + dq] =
                *(const float4*)&g_qkv[(size_t)(b * SEQ + kt + c) * FDIM
                                       + (NHEAD + NKV) * HD + kvh * HD + dq];
        }
        __syncthreads();

        // O += P V : 8 rows x 8 d-cols per thread
        #pragma unroll 2
        for (int c = 0; c < 128; ++c) {
            float4 v0 = *(const float4*)&KVs[c * 128 + tx * 8];
            float4 v1 = *(const float4*)&KVs[c * 128 + tx * 8 + 4];
            #pragma unroll
            for (int i = 0; i < 8; ++i) {
                float pv = Ps[(ty * 8 + i) * ATT_PS + c];
                O[i][0] += pv * v0.x; O[i][1] += pv * v0.y;
                O[i][2] += pv * v0.z; O[i][3] += pv * v0.w;
                O[i][4] += pv * v1.x; O[i][5] += pv * v1.y;
                O[i][6] += pv * v1.z; O[i][7] += pv * v1.w;
            }
        }
        __syncthreads();   // before next K tile overwrites KVs
    }

    #pragma unroll
    for (int i = 0; i < 8; ++i) {
        float inv_l = 1.f / l_i[i];
        int q = q0 + ty * 8 + i;
        float* yrow = &g_y[(size_t)(b * SEQ + q) * CDIM + h * HD + tx * 8];
        *(float4*)&yrow[0] = make_float4(O[i][0] * inv_l, O[i][1] * inv_l,
                                         O[i][2] * inv_l, O[i][3] * inv_l);
        *(float4*)&yrow[4] = make_float4(O[i][4] * inv_l, O[i][5] * inv_l,
                                         O[i][6] * inv_l, O[i][7] * inv_l);
    }
}

// ---------------------------------------------------------------------------
extern "C" void kernel_launch(void* const* d_in, const int* in_sizes, int n_in,
                              void* d_out, int out_size)
{
    (void)in_sizes; (void)n_in; (void)out_size;
    const float* x      = (const float*)d_in[0];
    const float* w_qkv  = (const float*)d_in[1];
    const float* w_proj = (const float*)d_in[2];
    const float* fcos   = (const float*)d_in[3];
    const float* fsin   = (const float*)d_in[4];
    float* out = (float*)d_out;

    void *p_qkv, *p_y, *p_xh, *p_xl, *p_wqh, *p_wql, *p_wph, *p_wpl, *p_yh, *p_yl;
    cudaGetSymbolAddress(&p_qkv, g_qkv);
    cudaGetSymbolAddress(&p_y,   g_y);
    cudaGetSymbolAddress(&p_xh,  g_xh);
    cudaGetSymbolAddress(&p_xl,  g_xl);
    cudaGetSymbolAddress(&p_wqh, g_wqh);
    cudaGetSymbolAddress(&p_wql, g_wql);
    cudaGetSymbolAddress(&p_wph, g_wph);
    cudaGetSymbolAddress(&p_wpl, g_wpl);
    cudaGetSymbolAddress(&p_yh,  g_yh);
    cudaGetSymbolAddress(&p_yl,  g_yl);

    cudaFuncSetAttribute(gemm_bf16x3_kernel,
                         cudaFuncAttributeMaxDynamicSharedMemorySize, GEMM_SMEM);
    cudaFuncSetAttribute(attn_kernel,
                         cudaFuncAttributeMaxDynamicSharedMemorySize, ATT_SMEM_FLOATS * 4);

    // splits
    {
        int n = MTOT * CDIM;
        split_kernel<<<(n + 255) / 256, 256>>>(x, (__nv_bfloat16*)p_xh, (__nv_bfloat16*)p_xl, n);
        n = FDIM * CDIM;
        split_kernel<<<(n + 255) / 256, 256>>>(w_qkv, (__nv_bfloat16*)p_wqh, (__nv_bfloat16*)p_wql, n);
        n = CDIM * CDIM;
        split_kernel<<<(n + 255) / 256, 256>>>(w_proj, (__nv_bfloat16*)p_wph, (__nv_bfloat16*)p_wpl, n);
    }
    // QKV projection (mma.sync bf16x3)
    {
        dim3 grid(FDIM / 128, MTOT / 128);
        gemm_bf16x3_kernel<<<grid, 256, GEMM_SMEM>>>(
            (const __nv_bfloat16*)p_xh, (const __nv_bfloat16*)p_xl,
            (const __nv_bfloat16*)p_wqh, (const __nv_bfloat16*)p_wql,
            (float*)p_qkv, MTOT, FDIM, CDIM);
    }
    // RoPE
    {
        int total = MTOT * (NHEAD + NKV) * (HD / 2);
        rope_kernel<<<(total + 255) / 256, 256>>>(fcos, fsin);
    }
    // Attention
    {
        dim3 grid(SEQ / 128, BATCH * NHEAD);
        attn_kernel<<<grid, 256, ATT_SMEM_FLOATS * 4>>>();
    }
    // split y, output projection
    {
        int n = MTOT * CDIM;
        split_kernel<<<(n + 255) / 256, 256>>>((const float*)p_y,
                                               (__nv_bfloat16*)p_yh, (__nv_bfloat16*)p_yl, n);
        dim3 grid(CDIM / 128, MTOT / 128);
        gemm_bf16x3_kernel<<<grid, 256, GEMM_SMEM>>>(
            (const __nv_bfloat16*)p_yh, (const __nv_bfloat16*)p_yl,
            (const __nv_bfloat16*)p_wph, (const __nv_bfloat16*)p_wpl,
            out, MTOT, CDIM, CDIM);
    }
}

// round 7
// speedup vs baseline: 2.5234x; 1.3037x over previous
#include <cuda_runtime.h>
#include <cuda_bf16.h>
#include <cstdint>
#include <math.h>

#define BATCH 2
#define SEQ   2048
#define CDIM  2048
#define NHEAD 16
#define NKV   4
#define HD    128
#define NREP  4
#define WIN   512
#define FDIM  3072
#define MTOT  (BATCH*SEQ)   // 4096
#define ATT_SCALE 0.08838834764831845f

// ---------------- scratch (__device__ globals; no allocations) -------------
__device__ float g_qkv[(size_t)MTOT * FDIM];           // 50.3 MB
__device__ __nv_bfloat16 g_xh[(size_t)MTOT * CDIM];
__device__ __nv_bfloat16 g_xl[(size_t)MTOT * CDIM];
__device__ __nv_bfloat16 g_wqh[(size_t)FDIM * CDIM];
__device__ __nv_bfloat16 g_wql[(size_t)FDIM * CDIM];
__device__ __nv_bfloat16 g_wph[(size_t)CDIM * CDIM];
__device__ __nv_bfloat16 g_wpl[(size_t)CDIM * CDIM];
__device__ __nv_bfloat16 g_yh[(size_t)MTOT * CDIM];
__device__ __nv_bfloat16 g_yl[(size_t)MTOT * CDIM];

// ---------------- helpers --------------------------------------------------
__device__ __forceinline__ uint32_t smem_to_u32(const void* p) {
    uint32_t a;
    asm("{ .reg .u64 t; cvta.to.shared.u64 t, %1; cvt.u32.u64 %0, t; }" : "=r"(a) : "l"(p));
    return a;
}
__device__ __forceinline__ void cp_async16(uint32_t dst, const void* src) {
    asm volatile("cp.async.cg.shared.global [%0], [%1], 16;" :: "r"(dst), "l"(src));
}
__device__ __forceinline__ void cp_commit() {
    asm volatile("cp.async.commit_group;");
}
template <int N>
__device__ __forceinline__ void cp_wait() {
    asm volatile("cp.async.wait_group %0;" :: "n"(N));
}
__device__ __forceinline__ void ldmatrix_x4(uint32_t* r, uint32_t addr) {
    asm volatile("ldmatrix.sync.aligned.m8n8.x4.shared.b16 {%0,%1,%2,%3}, [%4];"
        : "=r"(r[0]), "=r"(r[1]), "=r"(r[2]), "=r"(r[3]) : "r"(addr));
}
__device__ __forceinline__ void mma_bf16(float* c, const uint32_t* a, const uint32_t* b) {
    asm volatile(
        "mma.sync.aligned.m16n8k16.row.col.f32.bf16.bf16.f32 "
        "{%0,%1,%2,%3}, {%4,%5,%6,%7}, {%8,%9}, {%0,%1,%2,%3};"
        : "+f"(c[0]), "+f"(c[1]), "+f"(c[2]), "+f"(c[3])
        : "r"(a[0]), "r"(a[1]), "r"(a[2]), "r"(a[3]), "r"(b[0]), "r"(b[1]));
}
__device__ __forceinline__ uint32_t pack_bf16x2(float lo, float hi) {
    __nv_bfloat162 t = __floats2bfloat162_rn(lo, hi);
    return *(uint32_t*)&t;
}

// ---------------- split fp32 -> bf16 hi + bf16 lo --------------------------
__global__ void split_kernel(const float* __restrict__ src,
                             __nv_bfloat16* __restrict__ hi,
                             __nv_bfloat16* __restrict__ lo, int n)
{
    int i = blockIdx.x * blockDim.x + threadIdx.x;
    if (i >= n) return;
    float v = src[i];
    __nv_bfloat16 h = __float2bfloat16(v);
    hi[i] = h;
    lo[i] = __float2bfloat16(v - __bfloat162float(h));
}

// ---------------- bf16x3 NT GEMM via mma.sync (unchanged from R6) ----------
#define GPAD     40
#define GROW_B   (GPAD * 2)
#define GMAT_B   (128 * GROW_B)
#define GSTG_B   (4 * GMAT_B)
#define GEMM_SMEM (2 * GSTG_B)

__global__ void __launch_bounds__(256)
gemm_bf16x3_kernel(const __nv_bfloat16* __restrict__ Ah, const __nv_bfloat16* __restrict__ Al,
                   const __nv_bfloat16* __restrict__ Bh, const __nv_bfloat16* __restrict__ Bl,
                   float* __restrict__ C, int M, int N, int K)
{
    extern __shared__ __align__(128) char smem[];
    const uint32_t sbase = smem_to_u32(smem);

    const int tid  = threadIdx.x;
    const int wid  = tid >> 5;
    const int lane = tid & 31;
    const int warp_m = wid & 1;
    const int warp_n = wid >> 1;
    const int m0 = blockIdx.y * 128;
    const int n0 = blockIdx.x * 128;

    float acc[4][4][4];
    #pragma unroll
    for (int i = 0; i < 4; ++i)
        #pragma unroll
        for (int j = 0; j < 4; ++j)
            #pragma unroll
            for (int r = 0; r < 4; ++r) acc[i][j][r] = 0.f;

    const int NIT = K >> 5;

    auto issue_stage = [&](int it) {
        const int s = it & 1;
        const int k0 = it * 32;
        const char* gA[4] = {
            (const char*)(Ah + (size_t)m0 * K + k0), (const char*)(Al + (size_t)m0 * K + k0),
            (const char*)(Bh + (size_t)n0 * K + k0), (const char*)(Bl + (size_t)n0 * K + k0)};
        const size_t grs = (size_t)K * 2;
        #pragma unroll
        for (int t = 0; t < 4; ++t) {
            #pragma unroll
            for (int i = 0; i < 2; ++i) {
                int chunk = tid + i * 256;
                int r = chunk >> 2, c = (chunk & 3) * 16;
                uint32_t dst = sbase + s * GSTG_B + t * GMAT_B + r * GROW_B + c;
                cp_async16(dst, gA[t] + (size_t)r * grs + c);
            }
        }
        cp_commit();
    };

    issue_stage(0);

    for (int it = 0; it < NIT; ++it) {
        if (it + 1 < NIT) issue_stage(it + 1);
        if (it + 1 < NIT) cp_wait<1>(); else cp_wait<0>();
        __syncthreads();

        const int s = it & 1;
        const uint32_t sA_h = sbase + s * GSTG_B + 0 * GMAT_B;
        const uint32_t sA_l = sbase + s * GSTG_B + 1 * GMAT_B;
        const uint32_t sB_h = sbase + s * GSTG_B + 2 * GMAT_B;
        const uint32_t sB_l = sbase + s * GSTG_B + 3 * GMAT_B;

        const int lg = lane >> 3;
        #pragma unroll
        for (int ks = 0; ks < 2; ++ks) {
            const int kc = ks * 16;
            uint32_t ah[4][4], al[4][4];
            #pragma unroll
            for (int mt = 0; mt < 4; ++mt) {
                uint32_t off = (uint32_t)((warp_m * 64 + mt * 16 + (lane & 7) + (lg & 1) * 8) * GROW_B
                                          + (kc + (lg >> 1) * 8) * 2);
                ldmatrix_x4(ah[mt], sA_h + off);
                ldmatrix_x4(al[mt], sA_l + off);
            }
            uint32_t bh[2][4], bl[2][4];
            #pragma unroll
            for (int p = 0; p < 2; ++p) {
                uint32_t off = (uint32_t)((warp_n * 32 + p * 16 + (lane & 7) + (lg >> 1) * 8) * GROW_B
                                          + (kc + (lg & 1) * 8) * 2);
                ldmatrix_x4(bh[p], sB_h + off);
                ldmatrix_x4(bl[p], sB_l + off);
            }
            #pragma unroll
            for (int mt = 0; mt < 4; ++mt)
                #pragma unroll
                for (int nt = 0; nt < 4; ++nt) {
                    const uint32_t* bhp = &bh[nt >> 1][(nt & 1) * 2];
                    const uint32_t* blp = &bl[nt >> 1][(nt & 1) * 2];
                    mma_bf16(acc[mt][nt], ah[mt], bhp);
                    mma_bf16(acc[mt][nt], ah[mt], blp);
                    mma_bf16(acc[mt][nt], al[mt], bhp);
                }
        }
        __syncthreads();
    }

    #pragma unroll
    for (int mt = 0; mt < 4; ++mt) {
        #pragma unroll
        for (int nt = 0; nt < 4; ++nt) {
            int m = m0 + warp_m * 64 + mt * 16 + (lane >> 2);
            int n = n0 + warp_n * 32 + nt * 8 + (lane & 3) * 2;
            *(float2*)&C[(size_t)m * N + n]       = make_float2(acc[mt][nt][0], acc[mt][nt][1]);
            *(float2*)&C[(size_t)(m + 8) * N + n] = make_float2(acc[mt][nt][2], acc[mt][nt][3]);
        }
    }
}

// ---------------- RoPE -----------------------------------------------------
__global__ void rope_kernel(const float* __restrict__ fcos,
                            const float* __restrict__ fsin)
{
    const int PAIRS_PER_TOK = (NHEAD + NKV) * (HD / 2);
    int idx = blockIdx.x * blockDim.x + threadIdx.x;
    if (idx >= MTOT * PAIRS_PER_TOK) return;
    int tok = idx / PAIRS_PER_TOK;
    int r = idx % PAIRS_PER_TOK;
    int t = tok % SEQ;
    int h = r / (HD / 2);
    int p = r % (HD / 2);
    float c = __ldg(&fcos[t * (HD / 2) + p]);
    float s = __ldg(&fsin[t * (HD / 2) + p]);
    float* base = &g_qkv[(size_t)tok * FDIM + h * HD + 2 * p];
    float xr = base[0], xi = base[1];
    base[0] = xr * c - xi * s;
    base[1] = xr * s + xi * c;
}

// ---------------- windowed flash attention via mma.sync bf16x3 -------------
// CTA = 128 queries x one (b,h). 8 warps, each owns 16 q rows (FA-2 layout).
// smem: Qh,Ql,Kh,Kl (row=token, col=dim), Vh,Vl (row=dim, col=token).
#define AROW    136                 // elems per smem row (128 + 8 pad)
#define AROW_B  (AROW * 2)          // 272 bytes
#define ABUF_B  (128 * AROW_B)      // 34816
#define ATT_SMEM (6 * ABUF_B)       // 208896

__global__ void __launch_bounds__(256) attn_mma_kernel()
{
    extern __shared__ __align__(128) char asmem[];
    const uint32_t sb  = smem_to_u32(asmem);
    const uint32_t sQh = sb,              sQl = sb + ABUF_B;
    const uint32_t sKh = sb + 2*ABUF_B,   sKl = sb + 3*ABUF_B;
    const uint32_t sVh = sb + 4*ABUF_B,   sVl = sb + 5*ABUF_B;
    __nv_bfloat16* Qh = (__nv_bfloat16*)asmem;
    __nv_bfloat16* Ql = Qh + 128*AROW;
    __nv_bfloat16* Kh = Qh + 2*128*AROW;
    __nv_bfloat16* Kl = Qh + 3*128*AROW;
    __nv_bfloat16* Vh = Qh + 4*128*AROW;
    __nv_bfloat16* Vl = Qh + 5*128*AROW;

    const int tid  = threadIdx.x;
    const int w    = tid >> 5;
    const int lane = tid & 31;
    const int lg   = lane >> 3;
    const int bh   = blockIdx.y;
    const int b    = bh / NHEAD;
    const int h    = bh % NHEAD;
    const int kvh  = h / NREP;
    const int q0   = blockIdx.x * 128;

    // ---- load Q tile, split hi/lo (row=token, col=dim) ----
    #pragma unroll
    for (int i = 0; i < 16; ++i) {
        int v = tid + i * 256;
        int m = v >> 5, dq = (v & 31) * 4;
        float4 q = *(const float4*)&g_qkv[(size_t)(b * SEQ + q0 + m) * FDIM + h * HD + dq];
        float f[4] = {q.x, q.y, q.z, q.w};
        #pragma unroll
        for (int e = 0; e < 4; e += 2) {
            __nv_bfloat16 h0 = __float2bfloat16(f[e]);
            __nv_bfloat16 h1 = __float2bfloat16(f[e+1]);
            float l0 = f[e]   - __bfloat162float(h0);
            float l1 = f[e+1] - __bfloat162float(h1);
            *(uint32_t*)&Qh[m * AROW + dq + e] = pack_bf16x2(__bfloat162float(h0), __bfloat162float(h1));
            *(uint32_t*)&Ql[m * AROW + dq + e] = pack_bf16x2(l0, l1);
        }
    }

    float m_i[2] = {-1e30f, -1e30f};
    float l_i[2] = {0.f, 0.f};
    float oacc[16][4];
    #pragma unroll
    for (int i = 0; i < 16; ++i)
        #pragma unroll
        for (int r = 0; r < 4; ++r) oacc[i][r] = 0.f;

    const int row_r = q0 + w * 16 + (lane >> 2);   // first row this thread owns
    const int kt_lo = (q0 >= WIN) ? (q0 - WIN) : 0;

    for (int kt = kt_lo; kt <= q0; kt += 128) {
        __syncthreads();   // prior tile's smem reads done before overwrite
        // ---- load K (row=token) and V (transposed: row=dim) ----
        #pragma unroll
        for (int i = 0; i < 16; ++i) {
            int v = tid + i * 256;
            int c = v >> 5, dq = (v & 31) * 4;
            const size_t tokbase = (size_t)(b * SEQ + kt + c) * FDIM;
            float4 kk = *(const float4*)&g_qkv[tokbase + NHEAD * HD + kvh * HD + dq];
            float kf[4] = {kk.x, kk.y, kk.z, kk.w};
            #pragma unroll
            for (int e = 0; e < 4; e += 2) {
                __nv_bfloat16 h0 = __float2bfloat16(kf[e]);
                __nv_bfloat16 h1 = __float2bfloat16(kf[e+1]);
                *(uint32_t*)&Kh[c * AROW + dq + e] =
                    pack_bf16x2(__bfloat162float(h0), __bfloat162float(h1));
                *(uint32_t*)&Kl[c * AROW + dq + e] =
                    pack_bf16x2(kf[e] - __bfloat162float(h0), kf[e+1] - __bfloat162float(h1));
            }
            float4 vv = *(const float4*)&g_qkv[tokbase + (NHEAD + NKV) * HD + kvh * HD + dq];
            float vf[4] = {vv.x, vv.y, vv.z, vv.w};
            #pragma unroll
            for (int e = 0; e < 4; ++e) {
                __nv_bfloat16 vh = __float2bfloat16(vf[e]);
                Vh[(dq + e) * AROW + c] = vh;
                Vl[(dq + e) * AROW + c] = __float2bfloat16(vf[e] - __bfloat162float(vh));
            }
        }
        __syncthreads();

        // ---- S = Q K^T (3-term bf16) ----
        float sacc[16][4];
        #pragma unroll
        for (int i = 0; i < 16; ++i)
            #pragma unroll
            for (int r = 0; r < 4; ++r) sacc[i][r] = 0.f;

        #pragma unroll
        for (int ks = 0; ks < 8; ++ks) {
            uint32_t aQh[4], aQl[4];
            uint32_t aoff = (uint32_t)((w * 16 + (lane & 7) + (lg & 1) * 8) * AROW_B
                                       + (ks * 16 + (lg >> 1) * 8) * 2);
            ldmatrix_x4(aQh, sQh + aoff);
            ldmatrix_x4(aQl, sQl + aoff);
            #pragma unroll
            for (int p16 = 0; p16 < 8; ++p16) {
                uint32_t bK[4], bKl[4];
                uint32_t boff = (uint32_t)((p16 * 16 + (lane & 7) + (lg >> 1) * 8) * AROW_B
                                           + (ks * 16 + (lg & 1) * 8) * 2);
                ldmatrix_x4(bK,  sKh + boff);
                ldmatrix_x4(bKl, sKl + boff);
                mma_bf16(sacc[2*p16],   aQh, &bK[0]);
                mma_bf16(sacc[2*p16],   aQh, &bKl[0]);
                mma_bf16(sacc[2*p16],   aQl, &bK[0]);
                mma_bf16(sacc[2*p16+1], aQh, &bK[2]);
                mma_bf16(sacc[2*p16+1], aQh, &bKl[2]);
                mma_bf16(sacc[2*p16+1], aQl, &bK[2]);
            }
        }

        // ---- mask + scale ----
        #pragma unroll
        for (int nf = 0; nf < 16; ++nf) {
            int col = kt + nf * 8 + (lane & 3) * 2;
            #pragma unroll
            for (int e = 0; e < 2; ++e) {
                int cj = col + e;
                bool k0 = (cj <= row_r)     && (cj >= row_r - (WIN - 1));
                bool k1 = (cj <= row_r + 8) && (cj >= row_r + 8 - (WIN - 1));
                sacc[nf][e]     = k0 ? sacc[nf][e]     * ATT_SCALE : -1e30f;
                sacc[nf][e + 2] = k1 ? sacc[nf][e + 2] * ATT_SCALE : -1e30f;
            }
        }

        // ---- online softmax (rows r, r+8) ----
        float mx0 = -1e30f, mx1 = -1e30f;
        #pragma unroll
        for (int nf = 0; nf < 16; ++nf) {
            mx0 = fmaxf(mx0, fmaxf(sacc[nf][0], sacc[nf][1]));
            mx1 = fmaxf(mx1, fmaxf(sacc[nf][2], sacc[nf][3]));
        }
        #pragma unroll
        for (int o = 1; o < 4; o <<= 1) {
            mx0 = fmaxf(mx0, __shfl_xor_sync(0xffffffffu, mx0, o));
            mx1 = fmaxf(mx1, __shfl_xor_sync(0xffffffffu, mx1, o));
        }
        float mn0 = fmaxf(m_i[0], mx0), mn1 = fmaxf(m_i[1], mx1);
        float al0 = __expf(m_i[0] - mn0), al1 = __expf(m_i[1] - mn1);
        float rs0 = 0.f, rs1 = 0.f;
        #pragma unroll
        for (int nf = 0; nf < 16; ++nf) {
            sacc[nf][0] = __expf(sacc[nf][0] - mn0);
            sacc[nf][1] = __expf(sacc[nf][1] - mn0);
            sacc[nf][2] = __expf(sacc[nf][2] - mn1);
            sacc[nf][3] = __expf(sacc[nf][3] - mn1);
            rs0 += sacc[nf][0] + sacc[nf][1];
            rs1 += sacc[nf][2] + sacc[nf][3];
        }
        #pragma unroll
        for (int o = 1; o < 4; o <<= 1) {
            rs0 += __shfl_xor_sync(0xffffffffu, rs0, o);
            rs1 += __shfl_xor_sync(0xffffffffu, rs1, o);
        }
        l_i[0] = l_i[0] * al0 + rs0;  m_i[0] = mn0;
        l_i[1] = l_i[1] * al1 + rs1;  m_i[1] = mn1;
        #pragma unroll
        for (int nf = 0; nf < 16; ++nf) {
            oacc[nf][0] *= al0; oacc[nf][1] *= al0;
            oacc[nf][2] *= al1; oacc[nf][3] *= al1;
        }

        // ---- O += P V (3-term), streaming P fragments per k-chunk ----
        #pragma unroll
        for (int kc = 0; kc < 8; ++kc) {
            uint32_t aph[4], apl[4];
            #pragma unroll
            for (int half = 0; half < 2; ++half) {       // S frag 2kc, 2kc+1
                const float* sf = sacc[2 * kc + half];
                __nv_bfloat16 h0 = __float2bfloat16(sf[0]);
                __nv_bfloat16 h1 = __float2bfloat16(sf[1]);
                __nv_bfloat16 h2 = __float2bfloat16(sf[2]);
                __nv_bfloat16 h3 = __float2bfloat16(sf[3]);
                aph[half * 2 + 0] = pack_bf16x2(__bfloat162float(h0), __bfloat162float(h1));
                aph[half * 2 + 1] = pack_bf16x2(__bfloat162float(h2), __bfloat162float(h3));
                apl[half * 2 + 0] = pack_bf16x2(sf[0] - __bfloat162float(h0),
                                                sf[1] - __bfloat162float(h1));
                apl[half * 2 + 1] = pack_bf16x2(sf[2] - __bfloat162float(h2),
                                                sf[3] - __bfloat162float(h3));
            }
            // reorder: a0=(r,k0-7)=frag0 pair0; a1=(r+8,k0-7)=frag0 pair1;
            //          a2=(r,k8-15)=frag1 pair0; a3=(r+8,k8-15)=frag1 pair1  (already in order)
            #pragma unroll
            for (int p16 = 0; p16 < 8; ++p16) {
                uint32_t bV[4], bVl[4];
                uint32_t boff = (uint32_t)((p16 * 16 + (lane & 7) + (lg >> 1) * 8) * AROW_B
                                           + (kc * 16 + (lg & 1) * 8) * 2);
                ldmatrix_x4(bV,  sVh + boff);
                ldmatrix_x4(bVl, sVl + boff);
                mma_bf16(oacc[2*p16],   aph, &bV[0]);
                mma_bf16(oacc[2*p16],   aph, &bVl[0]);
                mma_bf16(oacc[2*p16],   apl, &bV[0]);
                mma_bf16(oacc[2*p16+1], aph, &bV[2]);
                mma_bf16(oacc[2*p16+1], aph, &bVl[2]);
                mma_bf16(oacc[2*p16+1], apl, &bV[2]);
            }
        }
    }

    // ---- normalize, split hi/lo, write y ----
    float inv0 = 1.f / l_i[0];
    float inv1 = 1.f / l_i[1];
    #pragma unroll
    for (int nf = 0; nf < 16; ++nf) {
        int d0 = nf * 8 + (lane & 3) * 2;
        size_t base0 = (size_t)(b * SEQ + row_r)     * CDIM + h * HD + d0;
        size_t base1 = (size_t)(b * SEQ + row_r + 8) * CDIM + h * HD + d0;
        float v00 = oacc[nf][0] * inv0, v01 = oacc[nf][1] * inv0;
        float v10 = oacc[nf][2] * inv1, v11 = oacc[nf][3] * inv1;
        __nv_bfloat16 h00 = __float2bfloat16(v00), h01 = __float2bfloat16(v01);
        __nv_bfloat16 h10 = __float2bfloat16(v10), h11 = __float2bfloat16(v11);
        *(uint32_t*)&g_yh[base0] = pack_bf16x2(__bfloat162float(h00), __bfloat162float(h01));
        *(uint32_t*)&g_yl[base0] = pack_bf16x2(v00 - __bfloat162float(h00),
                                               v01 - __bfloat162float(h01));
        *(uint32_t*)&g_yh[base1] = pack_bf16x2(__bfloat162float(h10), __bfloat162float(h11));
        *(uint32_t*)&g_yl[base1] = pack_bf16x2(v10 - __bfloat162float(h10),
                                               v11 - __bfloat162float(h11));
    }
}

// ---------------------------------------------------------------------------
extern "C" void kernel_launch(void* const* d_in, const int* in_sizes, int n_in,
                              void* d_out, int out_size)
{
    (void)in_sizes; (void)n_in; (void)out_size;
    const float* x      = (const float*)d_in[0];
    const float* w_qkv  = (const float*)d_in[1];
    const float* w_proj = (const float*)d_in[2];
    const float* fcos   = (const float*)d_in[3];
    const float* fsin   = (const float*)d_in[4];
    float* out = (float*)d_out;

    void *p_qkv, *p_xh, *p_xl, *p_wqh, *p_wql, *p_wph, *p_wpl, *p_yh, *p_yl;
    cudaGetSymbolAddress(&p_qkv, g_qkv);
    cudaGetSymbolAddress(&p_xh,  g_xh);
    cudaGetSymbolAddress(&p_xl,  g_xl);
    cudaGetSymbolAddress(&p_wqh, g_wqh);
    cudaGetSymbolAddress(&p_wql, g_wql);
    cudaGetSymbolAddress(&p_wph, g_wph);
    cudaGetSymbolAddress(&p_wpl, g_wpl);
    cudaGetSymbolAddress(&p_yh,  g_yh);
    cudaGetSymbolAddress(&p_yl,  g_yl);

    cudaFuncSetAttribute(gemm_bf16x3_kernel,
                         cudaFuncAttributeMaxDynamicSharedMemorySize, GEMM_SMEM);
    cudaFuncSetAttribute(attn_mma_kernel,
                         cudaFuncAttributeMaxDynamicSharedMemorySize, ATT_SMEM);

    // splits
    {
        int n = MTOT * CDIM;
        split_kernel<<<(n + 255) / 256, 256>>>(x, (__nv_bfloat16*)p_xh, (__nv_bfloat16*)p_xl, n);
        n = FDIM * CDIM;
        split_kernel<<<(n + 255) / 256, 256>>>(w_qkv, (__nv_bfloat16*)p_wqh, (__nv_bfloat16*)p_wql, n);
        n = CDIM * CDIM;
        split_kernel<<<(n + 255) / 256, 256>>>(w_proj, (__nv_bfloat16*)p_wph, (__nv_bfloat16*)p_wpl, n);
    }
    // QKV projection
    {
        dim3 grid(FDIM / 128, MTOT / 128);
        gemm_bf16x3_kernel<<<grid, 256, GEMM_SMEM>>>(
            (const __nv_bfloat16*)p_xh, (const __nv_bfloat16*)p_xl,
            (const __nv_bfloat16*)p_wqh, (const __nv_bfloat16*)p_wql,
            (float*)p_qkv, MTOT, FDIM, CDIM);
    }
    // RoPE
    {
        int total = MTOT * (NHEAD + NKV) * (HD / 2);
        rope_kernel<<<(total + 255) / 256, 256>>>(fcos, fsin);
    }
    // Attention (mma.sync, emits yh/yl directly)
    {
        dim3 grid(SEQ / 128, BATCH * NHEAD);
        attn_mma_kernel<<<grid, 256, ATT_SMEM>>>();
    }
    // Output projection
    {
        dim3 grid(CDIM / 128, MTOT / 128);
        gemm_bf16x3_kernel<<<grid, 256, GEMM_SMEM>>>(
            (const __nv_bfloat16*)p_yh, (const __nv_bfloat16*)p_yl,
            (const __nv_bfloat16*)p_wph, (const __nv_bfloat16*)p_wpl,
            out, MTOT, CDIM, CDIM);
    }
}

// round 8
// speedup vs baseline: 2.8561x; 1.1318x over previous
#include <cuda_runtime.h>
#include <cuda_bf16.h>
#include <cstdint>
#include <math.h>

#define BATCH 2
#define SEQ   2048
#define CDIM  2048
#define NHEAD 16
#define NKV   4
#define HD    128
#define NREP  4
#define WIN   512
#define FDIM  3072
#define MTOT  (BATCH*SEQ)   // 4096
#define ATT_SCALE 0.08838834764831845f

// ---------------- scratch (__device__ globals; no allocations) -------------
__device__ float g_qkv[(size_t)MTOT * FDIM];           // 50.3 MB
__device__ __nv_bfloat16 g_xh[(size_t)MTOT * CDIM];
__device__ __nv_bfloat16 g_xl[(size_t)MTOT * CDIM];
__device__ __nv_bfloat16 g_wqh[(size_t)FDIM * CDIM];
__device__ __nv_bfloat16 g_wql[(size_t)FDIM * CDIM];
__device__ __nv_bfloat16 g_wph[(size_t)CDIM * CDIM];
__device__ __nv_bfloat16 g_wpl[(size_t)CDIM * CDIM];
__device__ __nv_bfloat16 g_yh[(size_t)MTOT * CDIM];
__device__ __nv_bfloat16 g_yl[(size_t)MTOT * CDIM];

// ---------------- helpers --------------------------------------------------
__device__ __forceinline__ uint32_t smem_to_u32(const void* p) {
    uint32_t a;
    asm("{ .reg .u64 t; cvta.to.shared.u64 t, %1; cvt.u32.u64 %0, t; }" : "=r"(a) : "l"(p));
    return a;
}
__device__ __forceinline__ void cp_async16(uint32_t dst, const void* src) {
    asm volatile("cp.async.cg.shared.global [%0], [%1], 16;" :: "r"(dst), "l"(src));
}
__device__ __forceinline__ void cp_commit() {
    asm volatile("cp.async.commit_group;");
}
template <int N>
__device__ __forceinline__ void cp_wait() {
    asm volatile("cp.async.wait_group %0;" :: "n"(N));
}
__device__ __forceinline__ void ldmatrix_x4(uint32_t* r, uint32_t addr) {
    asm volatile("ldmatrix.sync.aligned.m8n8.x4.shared.b16 {%0,%1,%2,%3}, [%4];"
        : "=r"(r[0]), "=r"(r[1]), "=r"(r[2]), "=r"(r[3]) : "r"(addr));
}
__device__ __forceinline__ void ldmatrix_x4_trans(uint32_t* r, uint32_t addr) {
    asm volatile("ldmatrix.sync.aligned.m8n8.x4.trans.shared.b16 {%0,%1,%2,%3}, [%4];"
        : "=r"(r[0]), "=r"(r[1]), "=r"(r[2]), "=r"(r[3]) : "r"(addr));
}
__device__ __forceinline__ void mma_bf16(float* c, const uint32_t* a, const uint32_t* b) {
    asm volatile(
        "mma.sync.aligned.m16n8k16.row.col.f32.bf16.bf16.f32 "
        "{%0,%1,%2,%3}, {%4,%5,%6,%7}, {%8,%9}, {%0,%1,%2,%3};"
        : "+f"(c[0]), "+f"(c[1]), "+f"(c[2]), "+f"(c[3])
        : "r"(a[0]), "r"(a[1]), "r"(a[2]), "r"(a[3]), "r"(b[0]), "r"(b[1]));
}
__device__ __forceinline__ uint32_t pack_bf16x2(float lo, float hi) {
    __nv_bfloat162 t = __floats2bfloat162_rn(lo, hi);
    return *(uint32_t*)&t;
}

// ---------------- split fp32 -> bf16 hi + bf16 lo --------------------------
__global__ void split_kernel(const float* __restrict__ src,
                             __nv_bfloat16* __restrict__ hi,
                             __nv_bfloat16* __restrict__ lo, int n)
{
    int i = blockIdx.x * blockDim.x + threadIdx.x;
    if (i >= n) return;
    float v = src[i];
    __nv_bfloat16 h = __float2bfloat16(v);
    hi[i] = h;
    lo[i] = __float2bfloat16(v - __bfloat162float(h));
}

// ---------------- bf16x3 NT GEMM via mma.sync (unchanged, proven 55% TC) ---
#define GPAD     40
#define GROW_B   (GPAD * 2)
#define GMAT_B   (128 * GROW_B)
#define GSTG_B   (4 * GMAT_B)
#define GEMM_SMEM (2 * GSTG_B)

__global__ void __launch_bounds__(256)
gemm_bf16x3_kernel(const __nv_bfloat16* __restrict__ Ah, const __nv_bfloat16* __restrict__ Al,
                   const __nv_bfloat16* __restrict__ Bh, const __nv_bfloat16* __restrict__ Bl,
                   float* __restrict__ C, int M, int N, int K)
{
    extern __shared__ __align__(128) char smem[];
    const uint32_t sbase = smem_to_u32(smem);

    const int tid  = threadIdx.x;
    const int wid  = tid >> 5;
    const int lane = tid & 31;
    const int warp_m = wid & 1;
    const int warp_n = wid >> 1;
    const int m0 = blockIdx.y * 128;
    const int n0 = blockIdx.x * 128;

    float acc[4][4][4];
    #pragma unroll
    for (int i = 0; i < 4; ++i)
        #pragma unroll
        for (int j = 0; j < 4; ++j)
            #pragma unroll
            for (int r = 0; r < 4; ++r) acc[i][j][r] = 0.f;

    const int NIT = K >> 5;

    auto issue_stage = [&](int it) {
        const int s = it & 1;
        const int k0 = it * 32;
        const char* gA[4] = {
            (const char*)(Ah + (size_t)m0 * K + k0), (const char*)(Al + (size_t)m0 * K + k0),
            (const char*)(Bh + (size_t)n0 * K + k0), (const char*)(Bl + (size_t)n0 * K + k0)};
        const size_t grs = (size_t)K * 2;
        #pragma unroll
        for (int t = 0; t < 4; ++t) {
            #pragma unroll
            for (int i = 0; i < 2; ++i) {
                int chunk = tid + i * 256;
                int r = chunk >> 2, c = (chunk & 3) * 16;
                uint32_t dst = sbase + s * GSTG_B + t * GMAT_B + r * GROW_B + c;
                cp_async16(dst, gA[t] + (size_t)r * grs + c);
            }
        }
        cp_commit();
    };

    issue_stage(0);

    for (int it = 0; it < NIT; ++it) {
        if (it + 1 < NIT) issue_stage(it + 1);
        if (it + 1 < NIT) cp_wait<1>(); else cp_wait<0>();
        __syncthreads();

        const int s = it & 1;
        const uint32_t sA_h = sbase + s * GSTG_B + 0 * GMAT_B;
        const uint32_t sA_l = sbase + s * GSTG_B + 1 * GMAT_B;
        const uint32_t sB_h = sbase + s * GSTG_B + 2 * GMAT_B;
        const uint32_t sB_l = sbase + s * GSTG_B + 3 * GMAT_B;

        const int lg = lane >> 3;
        #pragma unroll
        for (int ks = 0; ks < 2; ++ks) {
            const int kc = ks * 16;
            uint32_t ah[4][4], al[4][4];
            #pragma unroll
            for (int mt = 0; mt < 4; ++mt) {
                uint32_t off = (uint32_t)((warp_m * 64 + mt * 16 + (lane & 7) + (lg & 1) * 8) * GROW_B
                                          + (kc + (lg >> 1) * 8) * 2);
                ldmatrix_x4(ah[mt], sA_h + off);
                ldmatrix_x4(al[mt], sA_l + off);
            }
            uint32_t bh[2][4], bl[2][4];
            #pragma unroll
            for (int p = 0; p < 2; ++p) {
                uint32_t off = (uint32_t)((warp_n * 32 + p * 16 + (lane & 7) + (lg >> 1) * 8) * GROW_B
                                          + (kc + (lg & 1) * 8) * 2);
                ldmatrix_x4(bh[p], sB_h + off);
                ldmatrix_x4(bl[p], sB_l + off);
            }
            #pragma unroll
            for (int mt = 0; mt < 4; ++mt)
                #pragma unroll
                for (int nt = 0; nt < 4; ++nt) {
                    const uint32_t* bhp = &bh[nt >> 1][(nt & 1) * 2];
                    const uint32_t* blp = &bl[nt >> 1][(nt & 1) * 2];
                    mma_bf16(acc[mt][nt], ah[mt], bhp);
                    mma_bf16(acc[mt][nt], ah[mt], blp);
                    mma_bf16(acc[mt][nt], al[mt], bhp);
                }
        }
        __syncthreads();
    }

    #pragma unroll
    for (int mt = 0; mt < 4; ++mt) {
        #pragma unroll
        for (int nt = 0; nt < 4; ++nt) {
            int m = m0 + warp_m * 64 + mt * 16 + (lane >> 2);
            int n = n0 + warp_n * 32 + nt * 8 + (lane & 3) * 2;
            *(float2*)&C[(size_t)m * N + n]       = make_float2(acc[mt][nt][0], acc[mt][nt][1]);
            *(float2*)&C[(size_t)(m + 8) * N + n] = make_float2(acc[mt][nt][2], acc[mt][nt][3]);
        }
    }
}

// ---------------- RoPE -----------------------------------------------------
__global__ void rope_kernel(const float* __restrict__ fcos,
                            const float* __restrict__ fsin)
{
    const int PAIRS_PER_TOK = (NHEAD + NKV) * (HD / 2);
    int idx = blockIdx.x * blockDim.x + threadIdx.x;
    if (idx >= MTOT * PAIRS_PER_TOK) return;
    int tok = idx / PAIRS_PER_TOK;
    int r = idx % PAIRS_PER_TOK;
    int t = tok % SEQ;
    int h = r / (HD / 2);
    int p = r % (HD / 2);
    float c = __ldg(&fcos[t * (HD / 2) + p]);
    float s = __ldg(&fsin[t * (HD / 2) + p]);
    float* base = &g_qkv[(size_t)tok * FDIM + h * HD + 2 * p];
    float xr = base[0], xi = base[1];
    base[0] = xr * c - xi * s;
    base[1] = xr * s + xi * c;
}

// ---------------- windowed flash attention via mma.sync bf16x3 -------------
// CTA = 128 queries x one (b,h). 8 warps, each owns 16 q rows (FA-2 layout).
// All tiles stored row=token, col=dim. PV uses ldmatrix.trans on V.
#define AROW    136                 // elems per smem row (128 + 8 pad)
#define AROW_B  (AROW * 2)          // 272 bytes
#define ABUF_B  (128 * AROW_B)      // 34816
#define ATT_SMEM (6 * ABUF_B)       // 208896

__global__ void __launch_bounds__(256) attn_mma_kernel()
{
    extern __shared__ __align__(128) char asmem[];
    const uint32_t sb  = smem_to_u32(asmem);
    const uint32_t sQh = sb,              sQl = sb + ABUF_B;
    const uint32_t sKh = sb + 2*ABUF_B,   sKl = sb + 3*ABUF_B;
    const uint32_t sVh = sb + 4*ABUF_B,   sVl = sb + 5*ABUF_B;
    __nv_bfloat16* Qh = (__nv_bfloat16*)asmem;
    __nv_bfloat16* Ql = Qh + 128*AROW;
    __nv_bfloat16* Kh = Qh + 2*128*AROW;
    __nv_bfloat16* Kl = Qh + 3*128*AROW;
    __nv_bfloat16* Vh = Qh + 4*128*AROW;
    __nv_bfloat16* Vl = Qh + 5*128*AROW;

    const int tid  = threadIdx.x;
    const int w    = tid >> 5;
    const int lane = tid & 31;
    const int lg   = lane >> 3;
    const int bh   = blockIdx.y;
    const int b    = bh / NHEAD;
    const int h    = bh % NHEAD;
    const int kvh  = h / NREP;
    const int q0   = blockIdx.x * 128;

    // ---- load Q tile, split hi/lo (row=token, col=dim) ----
    #pragma unroll
    for (int i = 0; i < 16; ++i) {
        int v = tid + i * 256;
        int m = v >> 5, dq = (v & 31) * 4;
        float4 q = *(const float4*)&g_qkv[(size_t)(b * SEQ + q0 + m) * FDIM + h * HD + dq];
        float f[4] = {q.x, q.y, q.z, q.w};
        #pragma unroll
        for (int e = 0; e < 4; e += 2) {
            __nv_bfloat16 h0 = __float2bfloat16(f[e]);
            __nv_bfloat16 h1 = __float2bfloat16(f[e+1]);
            float l0 = f[e]   - __bfloat162float(h0);
            float l1 = f[e+1] - __bfloat162float(h1);
            *(uint32_t*)&Qh[m * AROW + dq + e] = pack_bf16x2(__bfloat162float(h0), __bfloat162float(h1));
            *(uint32_t*)&Ql[m * AROW + dq + e] = pack_bf16x2(l0, l1);
        }
    }

    float m_i[2] = {-1e30f, -1e30f};
    float l_i[2] = {0.f, 0.f};
    float oacc[16][4];
    #pragma unroll
    for (int i = 0; i < 16; ++i)
        #pragma unroll
        for (int r = 0; r < 4; ++r) oacc[i][r] = 0.f;

    const int row_r = q0 + w * 16 + (lane >> 2);   // first row this thread owns
    const int kt_lo = (q0 >= WIN) ? (q0 - WIN) : 0;

    for (int kt = kt_lo; kt <= q0; kt += 128) {
        __syncthreads();   // prior tile's smem reads done before overwrite
        // ---- load K and V tiles, split hi/lo (both row=token, col=dim) ----
        #pragma unroll
        for (int i = 0; i < 16; ++i) {
            int v = tid + i * 256;
            int c = v >> 5, dq = (v & 31) * 4;
            const size_t tokbase = (size_t)(b * SEQ + kt + c) * FDIM;
            float4 kk = *(const float4*)&g_qkv[tokbase + NHEAD * HD + kvh * HD + dq];
            float kf[4] = {kk.x, kk.y, kk.z, kk.w};
            #pragma unroll
            for (int e = 0; e < 4; e += 2) {
                __nv_bfloat16 h0 = __float2bfloat16(kf[e]);
                __nv_bfloat16 h1 = __float2bfloat16(kf[e+1]);
                *(uint32_t*)&Kh[c * AROW + dq + e] =
                    pack_bf16x2(__bfloat162float(h0), __bfloat162float(h1));
                *(uint32_t*)&Kl[c * AROW + dq + e] =
                    pack_bf16x2(kf[e] - __bfloat162float(h0), kf[e+1] - __bfloat162float(h1));
            }
            float4 vv = *(const float4*)&g_qkv[tokbase + (NHEAD + NKV) * HD + kvh * HD + dq];
            float vf[4] = {vv.x, vv.y, vv.z, vv.w};
            #pragma unroll
            for (int e = 0; e < 4; e += 2) {
                __nv_bfloat16 h0 = __float2bfloat16(vf[e]);
                __nv_bfloat16 h1 = __float2bfloat16(vf[e+1]);
                *(uint32_t*)&Vh[c * AROW + dq + e] =
                    pack_bf16x2(__bfloat162float(h0), __bfloat162float(h1));
                *(uint32_t*)&Vl[c * AROW + dq + e] =
                    pack_bf16x2(vf[e] - __bfloat162float(h0), vf[e+1] - __bfloat162float(h1));
            }
        }
        __syncthreads();

        // ---- S = Q K^T (3-term bf16) ----
        float sacc[16][4];
        #pragma unroll
        for (int i = 0; i < 16; ++i)
            #pragma unroll
            for (int r = 0; r < 4; ++r) sacc[i][r] = 0.f;

        #pragma unroll
        for (int ks = 0; ks < 8; ++ks) {
            uint32_t aQh[4], aQl[4];
            uint32_t aoff = (uint32_t)((w * 16 + (lane & 7) + (lg & 1) * 8) * AROW_B
                                       + (ks * 16 + (lg >> 1) * 8) * 2);
            ldmatrix_x4(aQh, sQh + aoff);
            ldmatrix_x4(aQl, sQl + aoff);
            #pragma unroll
            for (int p16 = 0; p16 < 8; ++p16) {
                uint32_t bK[4], bKl[4];
                uint32_t boff = (uint32_t)((p16 * 16 + (lane & 7) + (lg >> 1) * 8) * AROW_B
                                           + (ks * 16 + (lg & 1) * 8) * 2);
                ldmatrix_x4(bK,  sKh + boff);
                ldmatrix_x4(bKl, sKl + boff);
                mma_bf16(sacc[2*p16],   aQh, &bK[0]);
                mma_bf16(sacc[2*p16],   aQh, &bKl[0]);
                mma_bf16(sacc[2*p16],   aQl, &bK[0]);
                mma_bf16(sacc[2*p16+1], aQh, &bK[2]);
                mma_bf16(sacc[2*p16+1], aQh, &bKl[2]);
                mma_bf16(sacc[2*p16+1], aQl, &bK[2]);
            }
        }

        // ---- mask + scale ----
        #pragma unroll
        for (int nf = 0; nf < 16; ++nf) {
            int col = kt + nf * 8 + (lane & 3) * 2;
            #pragma unroll
            for (int e = 0; e < 2; ++e) {
                int cj = col + e;
                bool k0 = (cj <= row_r)     && (cj >= row_r - (WIN - 1));
                bool k1 = (cj <= row_r + 8) && (cj >= row_r + 8 - (WIN - 1));
                sacc[nf][e]     = k0 ? sacc[nf][e]     * ATT_SCALE : -1e30f;
                sacc[nf][e + 2] = k1 ? sacc[nf][e + 2] * ATT_SCALE : -1e30f;
            }
        }

        // ---- online softmax (rows r, r+8) ----
        float mx0 = -1e30f, mx1 = -1e30f;
        #pragma unroll
        for (int nf = 0; nf < 16; ++nf) {
            mx0 = fmaxf(mx0, fmaxf(sacc[nf][0], sacc[nf][1]));
            mx1 = fmaxf(mx1, fmaxf(sacc[nf][2], sacc[nf][3]));
        }
        #pragma unroll
        for (int o = 1; o < 4; o <<= 1) {
            mx0 = fmaxf(mx0, __shfl_xor_sync(0xffffffffu, mx0, o));
            mx1 = fmaxf(mx1, __shfl_xor_sync(0xffffffffu, mx1, o));
        }
        float mn0 = fmaxf(m_i[0], mx0), mn1 = fmaxf(m_i[1], mx1);
        float al0 = __expf(m_i[0] - mn0), al1 = __expf(m_i[1] - mn1);
        float rs0 = 0.f, rs1 = 0.f;
        #pragma unroll
        for (int nf = 0; nf < 16; ++nf) {
            sacc[nf][0] = __expf(sacc[nf][0] - mn0);
            sacc[nf][1] = __expf(sacc[nf][1] - mn0);
            sacc[nf][2] = __expf(sacc[nf][2] - mn1);
            sacc[nf][3] = __expf(sacc[nf][3] - mn1);
            rs0 += sacc[nf][0] + sacc[nf][1];
            rs1 += sacc[nf][2] + sacc[nf][3];
        }
        #pragma unroll
        for (int o = 1; o < 4; o <<= 1) {
            rs0 += __shfl_xor_sync(0xffffffffu, rs0, o);
            rs1 += __shfl_xor_sync(0xffffffffu, rs1, o);
        }
        l_i[0] = l_i[0] * al0 + rs0;  m_i[0] = mn0;
        l_i[1] = l_i[1] * al1 + rs1;  m_i[1] = mn1;
        #pragma unroll
        for (int nf = 0; nf < 16; ++nf) {
            oacc[nf][0] *= al0; oacc[nf][1] *= al0;
            oacc[nf][2] *= al1; oacc[nf][3] *= al1;
        }

        // ---- O += P V (3-term), V fragments via ldmatrix.trans ----
        #pragma unroll
        for (int kc = 0; kc < 8; ++kc) {
            uint32_t aph[4], apl[4];
            #pragma unroll
            for (int half = 0; half < 2; ++half) {       // S frag 2kc, 2kc+1
                const float* sf = sacc[2 * kc + half];
                __nv_bfloat16 h0 = __float2bfloat16(sf[0]);
                __nv_bfloat16 h1 = __float2bfloat16(sf[1]);
                __nv_bfloat16 h2 = __float2bfloat16(sf[2]);
                __nv_bfloat16 h3 = __float2bfloat16(sf[3]);
                aph[half * 2 + 0] = pack_bf16x2(__bfloat162float(h0), __bfloat162float(h1));
                aph[half * 2 + 1] = pack_bf16x2(__bfloat162float(h2), __bfloat162float(h3));
                apl[half * 2 + 0] = pack_bf16x2(sf[0] - __bfloat162float(h0),
                                                sf[1] - __bfloat162float(h1));
                apl[half * 2 + 1] = pack_bf16x2(sf[2] - __bfloat162float(h2),
                                                sf[3] - __bfloat162float(h3));
            }
            #pragma unroll
            for (int p16 = 0; p16 < 8; ++p16) {
                // trans load: rows = tokens kc*16 + (lane&7) + (lg&1)*8,
                //             cols = dims p16*16 + (lg>>1)*8
                uint32_t bV[4], bVl[4];
                uint32_t boff = (uint32_t)((kc * 16 + (lane & 7) + (lg & 1) * 8) * AROW_B
                                           + (p16 * 16 + (lg >> 1) * 8) * 2);
                ldmatrix_x4_trans(bV,  sVh + boff);
                ldmatrix_x4_trans(bVl, sVl + boff);
                mma_bf16(oacc[2*p16],   aph, &bV[0]);
                mma_bf16(oacc[2*p16],   aph, &bVl[0]);
                mma_bf16(oacc[2*p16],   apl, &bV[0]);
                mma_bf16(oacc[2*p16+1], aph, &bV[2]);
                mma_bf16(oacc[2*p16+1], aph, &bVl[2]);
                mma_bf16(oacc[2*p16+1], apl, &bV[2]);
            }
        }
    }

    // ---- normalize, split hi/lo, write y ----
    float inv0 = 1.f / l_i[0];
    float inv1 = 1.f / l_i[1];
    #pragma unroll
    for (int nf = 0; nf < 16; ++nf) {
        int d0 = nf * 8 + (lane & 3) * 2;
        size_t base0 = (size_t)(b * SEQ + row_r)     * CDIM + h * HD + d0;
        size_t base1 = (size_t)(b * SEQ + row_r + 8) * CDIM + h * HD + d0;
        float v00 = oacc[nf][0] * inv0, v01 = oacc[nf][1] * inv0;
        float v10 = oacc[nf][2] * inv1, v11 = oacc[nf][3] * inv1;
        __nv_bfloat16 h00 = __float2bfloat16(v00), h01 = __float2bfloat16(v01);
        __nv_bfloat16 h10 = __float2bfloat16(v10), h11 = __float2bfloat16(v11);
        *(uint32_t*)&g_yh[base0] = pack_bf16x2(__bfloat162float(h00), __bfloat162float(h01));
        *(uint32_t*)&g_yl[base0] = pack_bf16x2(v00 - __bfloat162float(h00),
                                               v01 - __bfloat162float(h01));
        *(uint32_t*)&g_yh[base1] = pack_bf16x2(__bfloat162float(h10), __bfloat162float(h11));
        *(uint32_t*)&g_yl[base1] = pack_bf16x2(v10 - __bfloat162float(h10),
                                               v11 - __bfloat162float(h11));
    }
}

// ---------------------------------------------------------------------------
extern "C" void kernel_launch(void* const* d_in, const int* in_sizes, int n_in,
                              void* d_out, int out_size)
{
    (void)in_sizes; (void)n_in; (void)out_size;
    const float* x      = (const float*)d_in[0];
    const float* w_qkv  = (const float*)d_in[1];
    const float* w_proj = (const float*)d_in[2];
    const float* fcos   = (const float*)d_in[3];
    const float* fsin   = (const float*)d_in[4];
    float* out = (float*)d_out;

    void *p_qkv, *p_xh, *p_xl, *p_wqh, *p_wql, *p_wph, *p_wpl, *p_yh, *p_yl;
    cudaGetSymbolAddress(&p_qkv, g_qkv);
    cudaGetSymbolAddress(&p_xh,  g_xh);
    cudaGetSymbolAddress(&p_xl,  g_xl);
    cudaGetSymbolAddress(&p_wqh, g_wqh);
    cudaGetSymbolAddress(&p_wql, g_wql);
    cudaGetSymbolAddress(&p_wph, g_wph);
    cudaGetSymbolAddress(&p_wpl, g_wpl);
    cudaGetSymbolAddress(&p_yh,  g_yh);
    cudaGetSymbolAddress(&p_yl,  g_yl);

    cudaFuncSetAttribute(gemm_bf16x3_kernel,
                         cudaFuncAttributeMaxDynamicSharedMemorySize, GEMM_SMEM);
    cudaFuncSetAttribute(attn_mma_kernel,
                         cudaFuncAttributeMaxDynamicSharedMemorySize, ATT_SMEM);

    // splits
    {
        int n = MTOT * CDIM;
        split_kernel<<<(n + 255) / 256, 256>>>(x, (__nv_bfloat16*)p_xh, (__nv_bfloat16*)p_xl, n);
        n = FDIM * CDIM;
        split_kernel<<<(n + 255) / 256, 256>>>(w_qkv, (__nv_bfloat16*)p_wqh, (__nv_bfloat16*)p_wql, n);
        n = CDIM * CDIM;
        split_kernel<<<(n + 255) / 256, 256>>>(w_proj, (__nv_bfloat16*)p_wph, (__nv_bfloat16*)p_wpl, n);
    }
    // QKV projection
    {
        dim3 grid(FDIM / 128, MTOT / 128);
        gemm_bf16x3_kernel<<<grid, 256, GEMM_SMEM>>>(
            (const __nv_bfloat16*)p_xh, (const __nv_bfloat16*)p_xl,
            (const __nv_bfloat16*)p_wqh, (const __nv_bfloat16*)p_wql,
            (float*)p_qkv, MTOT, FDIM, CDIM);
    }
    // RoPE
    {
        int total = MTOT * (NHEAD + NKV) * (HD / 2);
        rope_kernel<<<(total + 255) / 256, 256>>>(fcos, fsin);
    }
    // Attention (mma.sync, ldmatrix.trans V, emits yh/yl directly)
    {
        dim3 grid(SEQ / 128, BATCH * NHEAD);
        attn_mma_kernel<<<grid, 256, ATT_SMEM>>>();
    }
    // Output projection
    {
        dim3 grid(CDIM / 128, MTOT / 128);
        gemm_bf16x3_kernel<<<grid, 256, GEMM_SMEM>>>(
            (const __nv_bfloat16*)p_yh, (const __nv_bfloat16*)p_yl,
            (const __nv_bfloat16*)p_wph, (const __nv_bfloat16*)p_wpl,
            out, MTOT, CDIM, CDIM);
    }
}